// round 2
// baseline (speedup 1.0000x reference)
#include <cuda_runtime.h>
#include <cuda_bf16.h>

#define NQ 4
#define NL 2
#define NT 256

__device__ float d_A[256];  // Re(U^dag Z0 U), 16x16 symmetric

__device__ __forceinline__ float2 cmul(float2 a, float2 b) {
    return make_float2(a.x * b.x - a.y * b.y, a.x * b.y + a.y * b.x);
}
__device__ __forceinline__ float2 cadd(float2 a, float2 b) {
    return make_float2(a.x + b.x, a.y + b.y);
}

// Build the fixed 16x16 circuit matrix U from qweights, then A = Re(U^dag Z0 U).
// Convention: state index k = w0<<3 | w1<<2 | w2<<1 | w3 (wire i -> bit 3-i).
__global__ void qnn_setup_kernel(const float* __restrict__ qw) {
    __shared__ float2 U[16][16];
    int t = threadIdx.x;  // 256 threads
    {
        int r = t >> 4, c = t & 15;
        U[r][c] = make_float2(r == c ? 1.f : 0.f, 0.f);
    }
    __syncthreads();

    for (int l = 0; l < NL; l++) {
        for (int i = 0; i < NQ; i++) {
            float phi = qw[(l * NQ + i) * 3 + 0];
            float th  = qw[(l * NQ + i) * 3 + 1];
            float om  = qw[(l * NQ + i) * 3 + 2];
            float ct = cosf(0.5f * th), st = sinf(0.5f * th);
            float ap = 0.5f * (phi + om), am = 0.5f * (phi - om);
            float cap = cosf(ap), sap = sinf(ap);
            float cam = cosf(am), sam = sinf(am);
            // Rot(phi,theta,omega) = RZ(om) RY(th) RZ(phi)
            float2 g00 = make_float2( cap * ct, -sap * ct);  //  e^{-i ap} ct
            float2 g01 = make_float2(-cam * st, -sam * st);  // -e^{+i am} st
            float2 g10 = make_float2( cam * st, -sam * st);  //  e^{-i am} st
            float2 g11 = make_float2( cap * ct,  sap * ct);  //  e^{+i ap} ct
            int bit = 3 - i;
            if (t < 128) {
                int pair = t >> 4;  // 8 row-pairs
                int c = t & 15;
                int low = pair & ((1 << bit) - 1);
                int hi  = pair >> bit;
                int r0  = (hi << (bit + 1)) | low;
                int r1  = r0 | (1 << bit);
                float2 u0 = U[r0][c], u1 = U[r1][c];
                U[r0][c] = cadd(cmul(g00, u0), cmul(g01, u1));
                U[r1][c] = cadd(cmul(g10, u0), cmul(g11, u1));
            }
            __syncthreads();
        }
        // CZ chain on wires (0,1),(1,2),(2,3) -> bit pairs (3,2),(2,1),(1,0)
        {
            int r = t >> 4, c = t & 15;
            float sign = 1.f;
            if (((r >> 3) & 1) && ((r >> 2) & 1)) sign = -sign;
            if (((r >> 2) & 1) && ((r >> 1) & 1)) sign = -sign;
            if (((r >> 1) & 1) && (r & 1))        sign = -sign;
            U[r][c].x *= sign;
            U[r][c].y *= sign;
        }
        __syncthreads();
    }

    // A[j][k] = sum_r z(r) * Re(conj(U[r][j]) * U[r][k]),  z(r) = (r&8)? -1 : +1
    int j = t >> 4, k = t & 15;
    float acc = 0.f;
    #pragma unroll
    for (int r = 0; r < 16; r++) {
        float z = (r & 8) ? -1.f : 1.f;
        acc += z * (U[r][j].x * U[r][k].x + U[r][j].y * U[r][k].y);
    }
    d_A[j * 16 + k] = acc;
}

__global__ __launch_bounds__(NT) void qnn_main_kernel(
    const float* __restrict__ text, const float* __restrict__ image,
    const float* __restrict__ tW1, const float* __restrict__ tb1,
    const float* __restrict__ tW2, const float* __restrict__ tb2,
    const float* __restrict__ iW1, const float* __restrict__ ib1,
    const float* __restrict__ iW2, const float* __restrict__ ib2,
    const float* __restrict__ cW1, const float* __restrict__ cb1,
    const float* __restrict__ cW2, const float* __restrict__ cb2,
    float* __restrict__ out)
{
    __shared__ __align__(16) float s_tW1[16 * 32];
    __shared__ __align__(16) float s_tb1[32];
    __shared__ __align__(16) float s_tW2[32 * 4];
    __shared__ __align__(16) float s_iW1[48 * 64];
    __shared__ __align__(16) float s_ib1[64];
    __shared__ __align__(16) float s_iW2[64 * 4];
    __shared__ __align__(16) float s_A[256];
    __shared__ float s_tb2[4], s_ib2[4];
    __shared__ float s_cW1[16], s_cb1[16], s_cW2[32], s_cb2[2];

    int tid = threadIdx.x;
    for (int i = tid; i < 512; i += NT) s_tW1[i] = tW1[i];
    for (int i = tid; i < 3072; i += NT) s_iW1[i] = iW1[i];
    for (int i = tid; i < 256; i += NT) { s_iW2[i] = iW2[i]; s_A[i] = d_A[i]; }
    for (int i = tid; i < 128; i += NT) s_tW2[i] = tW2[i];
    if (tid < 64) s_ib1[tid] = ib1[tid];
    if (tid < 32) { s_tb1[tid] = tb1[tid]; s_cW2[tid] = cW2[tid]; }
    if (tid < 16) { s_cW1[tid] = cW1[tid]; s_cb1[tid] = cb1[tid]; }
    if (tid < 4) { s_tb2[tid] = tb2[tid]; s_ib2[tid] = ib2[tid]; }
    if (tid < 2) s_cb2[tid] = cb2[tid];
    __syncthreads();

    int b = blockIdx.x * NT + tid;

    // ---- feats accumulators: tf + imf (both biases folded in) ----
    float acc0 = s_tb2[0] + s_ib2[0];
    float acc1 = s_tb2[1] + s_ib2[1];
    float acc2 = s_tb2[2] + s_ib2[2];
    float acc3 = s_tb2[3] + s_ib2[3];

    // ---- text MLP: 16 -> 32 (relu) -> 4 ----
    {
        float tx[16];
        const float4* t4 = (const float4*)(text + (size_t)b * 16);
        #pragma unroll
        for (int k = 0; k < 4; k++) {
            float4 v = t4[k];
            tx[4 * k + 0] = v.x; tx[4 * k + 1] = v.y;
            tx[4 * k + 2] = v.z; tx[4 * k + 3] = v.w;
        }
        #pragma unroll
        for (int j = 0; j < 32; j += 4) {
            float4 h = *(const float4*)&s_tb1[j];
            #pragma unroll
            for (int k = 0; k < 16; k++) {
                float4 w = *(const float4*)&s_tW1[k * 32 + j];
                h.x = fmaf(tx[k], w.x, h.x);
                h.y = fmaf(tx[k], w.y, h.y);
                h.z = fmaf(tx[k], w.z, h.z);
                h.w = fmaf(tx[k], w.w, h.w);
            }
            h.x = fmaxf(h.x, 0.f); h.y = fmaxf(h.y, 0.f);
            h.z = fmaxf(h.z, 0.f); h.w = fmaxf(h.w, 0.f);
            float4 w0 = *(const float4*)&s_tW2[(j + 0) * 4];
            float4 w1 = *(const float4*)&s_tW2[(j + 1) * 4];
            float4 w2 = *(const float4*)&s_tW2[(j + 2) * 4];
            float4 w3 = *(const float4*)&s_tW2[(j + 3) * 4];
            acc0 = fmaf(h.x, w0.x, acc0); acc1 = fmaf(h.x, w0.y, acc1);
            acc2 = fmaf(h.x, w0.z, acc2); acc3 = fmaf(h.x, w0.w, acc3);
            acc0 = fmaf(h.y, w1.x, acc0); acc1 = fmaf(h.y, w1.y, acc1);
            acc2 = fmaf(h.y, w1.z, acc2); acc3 = fmaf(h.y, w1.w, acc3);
            acc0 = fmaf(h.z, w2.x, acc0); acc1 = fmaf(h.z, w2.y, acc1);
            acc2 = fmaf(h.z, w2.z, acc2); acc3 = fmaf(h.z, w2.w, acc3);
            acc0 = fmaf(h.w, w3.x, acc0); acc1 = fmaf(h.w, w3.y, acc1);
            acc2 = fmaf(h.w, w3.z, acc2); acc3 = fmaf(h.w, w3.w, acc3);
        }
    }

    // ---- image MLP: 48 -> 64 (relu) -> 4 ----
    {
        float ix[48];
        const float4* i4 = (const float4*)(image + (size_t)b * 48);
        #pragma unroll
        for (int k = 0; k < 12; k++) {
            float4 v = i4[k];
            ix[4 * k + 0] = v.x; ix[4 * k + 1] = v.y;
            ix[4 * k + 2] = v.z; ix[4 * k + 3] = v.w;
        }
        #pragma unroll 2
        for (int j = 0; j < 64; j += 4) {
            float4 h = *(const float4*)&s_ib1[j];
            #pragma unroll
            for (int k = 0; k < 48; k++) {
                float4 w = *(const float4*)&s_iW1[k * 64 + j];
                h.x = fmaf(ix[k], w.x, h.x);
                h.y = fmaf(ix[k], w.y, h.y);
                h.z = fmaf(ix[k], w.z, h.z);
                h.w = fmaf(ix[k], w.w, h.w);
            }
            h.x = fmaxf(h.x, 0.f); h.y = fmaxf(h.y, 0.f);
            h.z = fmaxf(h.z, 0.f); h.w = fmaxf(h.w, 0.f);
            float4 w0 = *(const float4*)&s_iW2[(j + 0) * 4];
            float4 w1 = *(const float4*)&s_iW2[(j + 1) * 4];
            float4 w2 = *(const float4*)&s_iW2[(j + 2) * 4];
            float4 w3 = *(const float4*)&s_iW2[(j + 3) * 4];
            acc0 = fmaf(h.x, w0.x, acc0); acc1 = fmaf(h.x, w0.y, acc1);
            acc2 = fmaf(h.x, w0.z, acc2); acc3 = fmaf(h.x, w0.w, acc3);
            acc0 = fmaf(h.y, w1.x, acc0); acc1 = fmaf(h.y, w1.y, acc1);
            acc2 = fmaf(h.y, w1.z, acc2); acc3 = fmaf(h.y, w1.w, acc3);
            acc0 = fmaf(h.z, w2.x, acc0); acc1 = fmaf(h.z, w2.y, acc1);
            acc2 = fmaf(h.z, w2.z, acc2); acc3 = fmaf(h.z, w2.w, acc3);
            acc0 = fmaf(h.w, w3.x, acc0); acc1 = fmaf(h.w, w3.y, acc1);
            acc2 = fmaf(h.w, w3.z, acc2); acc3 = fmaf(h.w, w3.w, acc3);
        }
    }

    // ---- quantum: feats = 0.5*(tf+imf); half-angle = 0.25*acc ----
    float cc[4], ss[4];
    {
        float a[4] = {0.25f * acc0, 0.25f * acc1, 0.25f * acc2, 0.25f * acc3};
        #pragma unroll
        for (int i = 0; i < 4; i++) {
            __sincosf(a[i], &ss[i], &cc[i]);
            // use accurate variants; override below
        }
        // accurate sin/cos (fast path above is discarded by recompute)
        #pragma unroll
        for (int i = 0; i < 4; i++) { sincosf(a[i], &ss[i], &cc[i]); }
    }
    float e01[4] = {cc[0] * cc[1], cc[0] * ss[1], ss[0] * cc[1], ss[0] * ss[1]};
    float e23[4] = {cc[2] * cc[3], cc[2] * ss[3], ss[2] * cc[3], ss[2] * ss[3]};
    float psi[16];
    #pragma unroll
    for (int k = 0; k < 16; k++) psi[k] = e01[k >> 2] * e23[k & 3];

    float q = 0.f;
    #pragma unroll
    for (int j = 0; j < 16; j++) {
        float tj = 0.f;
        #pragma unroll
        for (int k = 0; k < 16; k += 4) {
            float4 a = *(const float4*)&s_A[j * 16 + k];
            tj = fmaf(psi[k + 0], a.x, tj);
            tj = fmaf(psi[k + 1], a.y, tj);
            tj = fmaf(psi[k + 2], a.z, tj);
            tj = fmaf(psi[k + 3], a.w, tj);
        }
        q = fmaf(psi[j], tj, q);
    }

    // ---- classifier: q -> 16 (relu) -> 2 ----
    float o0 = s_cb2[0], o1 = s_cb2[1];
    #pragma unroll
    for (int m = 0; m < 16; m++) {
        float h = fmaxf(fmaf(q, s_cW1[m], s_cb1[m]), 0.f);
        o0 = fmaf(h, s_cW2[2 * m + 0], o0);
        o1 = fmaf(h, s_cW2[2 * m + 1], o1);
    }
    ((float2*)out)[b] = make_float2(o0, o1);
}

extern "C" void kernel_launch(void* const* d_in, const int* in_sizes, int n_in,
                              void* d_out, int out_size) {
    const float* text = (const float*)d_in[0];
    const float* image = (const float*)d_in[1];
    const float* tW1 = (const float*)d_in[2];
    const float* tb1 = (const float*)d_in[3];
    const float* tW2 = (const float*)d_in[4];
    const float* tb2 = (const float*)d_in[5];
    const float* iW1 = (const float*)d_in[6];
    const float* ib1 = (const float*)d_in[7];
    const float* iW2 = (const float*)d_in[8];
    const float* ib2 = (const float*)d_in[9];
    const float* qweights = (const float*)d_in[10];
    const float* cW1 = (const float*)d_in[11];
    const float* cb1 = (const float*)d_in[12];
    const float* cW2 = (const float*)d_in[13];
    const float* cb2 = (const float*)d_in[14];
    float* out = (float*)d_out;

    int B = in_sizes[0] / 16;  // 524288
    qnn_setup_kernel<<<1, 256>>>(qweights);
    qnn_main_kernel<<<B / NT, NT>>>(text, image, tW1, tb1, tW2, tb2,
                                    iW1, ib1, iW2, ib2,
                                    cW1, cb1, cW2, cb2, out);
}

// round 5
// speedup vs baseline: 1.0591x; 1.0591x over previous
#include <cuda_runtime.h>
#include <cuda_bf16.h>

#define NQ 4
#define NL 2
#define NT 256

typedef unsigned long long ull;

__device__ float d_A[256];  // Re(U^dag Z0 U), 16x16 symmetric

__device__ __forceinline__ ull pack2(float lo, float hi) {
    ull r; asm("mov.b64 %0, {%1, %2};" : "=l"(r) : "f"(lo), "f"(hi)); return r;
}
__device__ __forceinline__ ull dup2(float x) { return pack2(x, x); }
__device__ __forceinline__ void unpack2(ull v, float& lo, float& hi) {
    asm("mov.b64 {%0, %1}, %2;" : "=f"(lo), "=f"(hi) : "l"(v));
}
__device__ __forceinline__ ull ffma2(ull a, ull b, ull c) {
    ull d; asm("fma.rn.f32x2 %0, %1, %2, %3;" : "=l"(d) : "l"(a), "l"(b), "l"(c)); return d;
}
__device__ __forceinline__ ull fmul2(ull a, ull b) {
    ull d; asm("mul.rn.f32x2 %0, %1, %2;" : "=l"(d) : "l"(a), "l"(b)); return d;
}

__device__ __forceinline__ float2 cmul(float2 a, float2 b) {
    return make_float2(a.x * b.x - a.y * b.y, a.x * b.y + a.y * b.x);
}
__device__ __forceinline__ float2 cadd(float2 a, float2 b) {
    return make_float2(a.x + b.x, a.y + b.y);
}

// Build fixed 16x16 circuit unitary from qweights, then A = Re(U^dag Z0 U).
__global__ void qnn_setup_kernel(const float* __restrict__ qw) {
    __shared__ float2 U[16][16];
    int t = threadIdx.x;  // 256 threads
    {
        int r = t >> 4, c = t & 15;
        U[r][c] = make_float2(r == c ? 1.f : 0.f, 0.f);
    }
    __syncthreads();

    for (int l = 0; l < NL; l++) {
        for (int i = 0; i < NQ; i++) {
            float phi = qw[(l * NQ + i) * 3 + 0];
            float th  = qw[(l * NQ + i) * 3 + 1];
            float om  = qw[(l * NQ + i) * 3 + 2];
            float ct = cosf(0.5f * th), st = sinf(0.5f * th);
            float ap = 0.5f * (phi + om), am = 0.5f * (phi - om);
            float cap = cosf(ap), sap = sinf(ap);
            float cam = cosf(am), sam = sinf(am);
            float2 g00 = make_float2( cap * ct, -sap * ct);
            float2 g01 = make_float2(-cam * st, -sam * st);
            float2 g10 = make_float2( cam * st, -sam * st);
            float2 g11 = make_float2( cap * ct,  sap * ct);
            int bit = 3 - i;
            if (t < 128) {
                int pair = t >> 4;
                int c = t & 15;
                int low = pair & ((1 << bit) - 1);
                int hi  = pair >> bit;
                int r0  = (hi << (bit + 1)) | low;
                int r1  = r0 | (1 << bit);
                float2 u0 = U[r0][c], u1 = U[r1][c];
                U[r0][c] = cadd(cmul(g00, u0), cmul(g01, u1));
                U[r1][c] = cadd(cmul(g10, u0), cmul(g11, u1));
            }
            __syncthreads();
        }
        {
            int r = t >> 4, c = t & 15;
            float sign = 1.f;
            if (((r >> 3) & 1) && ((r >> 2) & 1)) sign = -sign;
            if (((r >> 2) & 1) && ((r >> 1) & 1)) sign = -sign;
            if (((r >> 1) & 1) && (r & 1))        sign = -sign;
            U[r][c].x *= sign;
            U[r][c].y *= sign;
        }
        __syncthreads();
    }

    int j = t >> 4, k = t & 15;
    float acc = 0.f;
    #pragma unroll
    for (int r = 0; r < 16; r++) {
        float z = (r & 8) ? -1.f : 1.f;
        acc += z * (U[r][j].x * U[r][k].x + U[r][j].y * U[r][k].y);
    }
    d_A[j * 16 + k] = acc;
}

__global__ __launch_bounds__(NT) void qnn_main_kernel(
    const float* __restrict__ text, const float* __restrict__ image,
    const float* __restrict__ tW1, const float* __restrict__ tb1,
    const float* __restrict__ tW2, const float* __restrict__ tb2,
    const float* __restrict__ iW1, const float* __restrict__ ib1,
    const float* __restrict__ iW2, const float* __restrict__ ib2,
    const float* __restrict__ cW1, const float* __restrict__ cb1,
    const float* __restrict__ cW2, const float* __restrict__ cb2,
    float* __restrict__ out)
{
    __shared__ __align__(16) float s_tW1[16 * 32];
    __shared__ __align__(16) float s_tb1[32];
    __shared__ __align__(16) float s_tW2[32 * 4];
    __shared__ __align__(16) float s_iW1[48 * 64];
    __shared__ __align__(16) float s_ib1[64];
    __shared__ __align__(16) float s_iW2[64 * 4];
    __shared__ __align__(16) float s_A[256];
    __shared__ float s_tb2[4], s_ib2[4];
    __shared__ float s_cW1[16], s_cb1[16], s_cW2[32], s_cb2[2];

    int tid = threadIdx.x;
    for (int i = tid; i < 512; i += NT) s_tW1[i] = tW1[i];
    for (int i = tid; i < 3072; i += NT) s_iW1[i] = iW1[i];
    for (int i = tid; i < 256; i += NT) { s_iW2[i] = iW2[i]; s_A[i] = d_A[i]; }
    for (int i = tid; i < 128; i += NT) s_tW2[i] = tW2[i];
    if (tid < 64) s_ib1[tid] = ib1[tid];
    if (tid < 32) { s_tb1[tid] = tb1[tid]; s_cW2[tid] = cW2[tid]; }
    if (tid < 16) { s_cW1[tid] = cW1[tid]; s_cb1[tid] = cb1[tid]; }
    if (tid < 4) { s_tb2[tid] = tb2[tid]; s_ib2[tid] = ib2[tid]; }
    if (tid < 2) s_cb2[tid] = cb2[tid];
    __syncthreads();

    int b = blockIdx.x * NT + tid;

    float acc0 = s_tb2[0] + s_ib2[0];
    float acc1 = s_tb2[1] + s_ib2[1];
    float acc2 = s_tb2[2] + s_ib2[2];
    float acc3 = s_tb2[3] + s_ib2[3];

    // ---- text MLP: 16 -> 32 (relu) -> 4, f32x2 over output pairs ----
    {
        ull h2[16];  // 32 hidden, packed as (j, j+1)
        {
            const ulonglong2* bb = (const ulonglong2*)s_tb1;
            #pragma unroll
            for (int p = 0; p < 8; p++) {
                ulonglong2 v = bb[p];
                h2[2 * p] = v.x; h2[2 * p + 1] = v.y;
            }
        }
        const float4* t4 = (const float4*)(text + (size_t)b * 16);
        float4 cur = t4[0];
        #pragma unroll
        for (int kb = 0; kb < 4; kb++) {
            float4 nxt = (kb < 3) ? t4[kb + 1] : cur;
            float xs[4] = {cur.x, cur.y, cur.z, cur.w};
            #pragma unroll
            for (int kk = 0; kk < 4; kk++) {
                int k = 4 * kb + kk;
                ull xd = dup2(xs[kk]);
                const ulonglong2* wrow = (const ulonglong2*)&s_tW1[k * 32];
                #pragma unroll
                for (int p = 0; p < 8; p++) {
                    ulonglong2 w = wrow[p];
                    h2[2 * p]     = ffma2(xd, w.x, h2[2 * p]);
                    h2[2 * p + 1] = ffma2(xd, w.y, h2[2 * p + 1]);
                }
            }
            cur = nxt;
        }
        // second layer 32 -> 4
        #pragma unroll
        for (int m = 0; m < 16; m++) {
            float ha, hb;
            unpack2(h2[m], ha, hb);
            ha = fmaxf(ha, 0.f); hb = fmaxf(hb, 0.f);
            float4 w0 = *(const float4*)&s_tW2[(2 * m) * 4];
            float4 w1 = *(const float4*)&s_tW2[(2 * m + 1) * 4];
            acc0 = fmaf(ha, w0.x, acc0); acc1 = fmaf(ha, w0.y, acc1);
            acc2 = fmaf(ha, w0.z, acc2); acc3 = fmaf(ha, w0.w, acc3);
            acc0 = fmaf(hb, w1.x, acc0); acc1 = fmaf(hb, w1.y, acc1);
            acc2 = fmaf(hb, w1.z, acc2); acc3 = fmaf(hb, w1.w, acc3);
        }
    }

    // ---- image MLP: 48 -> 64 (relu) -> 4, f32x2 over output pairs ----
    {
        ull h2[32];  // 64 hidden, packed as (j, j+1)
        {
            const ulonglong2* bb = (const ulonglong2*)s_ib1;
            #pragma unroll
            for (int p = 0; p < 16; p++) {
                ulonglong2 v = bb[p];
                h2[2 * p] = v.x; h2[2 * p + 1] = v.y;
            }
        }
        const float4* i4 = (const float4*)(image + (size_t)b * 48);
        float4 cur = i4[0];
        #pragma unroll 3
        for (int kb = 0; kb < 12; kb++) {
            float4 nxt = (kb < 11) ? i4[kb + 1] : cur;
            float xs[4] = {cur.x, cur.y, cur.z, cur.w};
            #pragma unroll
            for (int kk = 0; kk < 4; kk++) {
                int k = 4 * kb + kk;
                ull xd = dup2(xs[kk]);
                const ulonglong2* wrow = (const ulonglong2*)&s_iW1[k * 64];
                #pragma unroll
                for (int p = 0; p < 16; p++) {
                    ulonglong2 w = wrow[p];
                    h2[2 * p]     = ffma2(xd, w.x, h2[2 * p]);
                    h2[2 * p + 1] = ffma2(xd, w.y, h2[2 * p + 1]);
                }
            }
            cur = nxt;
        }
        // second layer 64 -> 4
        #pragma unroll
        for (int m = 0; m < 32; m++) {
            float ha, hb;
            unpack2(h2[m], ha, hb);
            ha = fmaxf(ha, 0.f); hb = fmaxf(hb, 0.f);
            float4 w0 = *(const float4*)&s_iW2[(2 * m) * 4];
            float4 w1 = *(const float4*)&s_iW2[(2 * m + 1) * 4];
            acc0 = fmaf(ha, w0.x, acc0); acc1 = fmaf(ha, w0.y, acc1);
            acc2 = fmaf(ha, w0.z, acc2); acc3 = fmaf(ha, w0.w, acc3);
            acc0 = fmaf(hb, w1.x, acc0); acc1 = fmaf(hb, w1.y, acc1);
            acc2 = fmaf(hb, w1.z, acc2); acc3 = fmaf(hb, w1.w, acc3);
        }
    }

    // ---- quantum: feats = 0.5*(tf+imf); half-angle = 0.25*acc ----
    float cc[4], ss[4];
    {
        float a[4] = {0.25f * acc0, 0.25f * acc1, 0.25f * acc2, 0.25f * acc3};
        #pragma unroll
        for (int i = 0; i < 4; i++) __sincosf(a[i], &ss[i], &cc[i]);
    }
    float e01[4] = {cc[0] * cc[1], cc[0] * ss[1], ss[0] * cc[1], ss[0] * ss[1]};
    ull e23a = pack2(cc[2] * cc[3], cc[2] * ss[3]);
    ull e23b = pack2(ss[2] * cc[3], ss[2] * ss[3]);

    ull psi2[8];
    float psi[16];
    #pragma unroll
    for (int j = 0; j < 4; j++) {
        ull ed = dup2(e01[j]);
        psi2[2 * j]     = fmul2(ed, e23a);
        psi2[2 * j + 1] = fmul2(ed, e23b);
        unpack2(psi2[2 * j],     psi[4 * j + 0], psi[4 * j + 1]);
        unpack2(psi2[2 * j + 1], psi[4 * j + 2], psi[4 * j + 3]);
    }

    float q = 0.f;
    #pragma unroll
    for (int j = 0; j < 16; j++) {
        ull tj2 = 0ULL;
        const ulonglong2* arow = (const ulonglong2*)&s_A[j * 16];
        #pragma unroll
        for (int p = 0; p < 4; p++) {
            ulonglong2 a2 = arow[p];
            tj2 = ffma2(psi2[2 * p],     a2.x, tj2);
            tj2 = ffma2(psi2[2 * p + 1], a2.y, tj2);
        }
        float ta, tb;
        unpack2(tj2, ta, tb);
        q = fmaf(psi[j], ta + tb, q);
    }

    // ---- classifier: q -> 16 (relu) -> 2 ----
    float o0 = s_cb2[0], o1 = s_cb2[1];
    #pragma unroll
    for (int m = 0; m < 16; m++) {
        float h = fmaxf(fmaf(q, s_cW1[m], s_cb1[m]), 0.f);
        o0 = fmaf(h, s_cW2[2 * m + 0], o0);
        o1 = fmaf(h, s_cW2[2 * m + 1], o1);
    }
    ((float2*)out)[b] = make_float2(o0, o1);
}

extern "C" void kernel_launch(void* const* d_in, const int* in_sizes, int n_in,
                              void* d_out, int out_size) {
    const float* text = (const float*)d_in[0];
    const float* image = (const float*)d_in[1];
    const float* tW1 = (const float*)d_in[2];
    const float* tb1 = (const float*)d_in[3];
    const float* tW2 = (const float*)d_in[4];
    const float* tb2 = (const float*)d_in[5];
    const float* iW1 = (const float*)d_in[6];
    const float* ib1 = (const float*)d_in[7];
    const float* iW2 = (const float*)d_in[8];
    const float* ib2 = (const float*)d_in[9];
    const float* qweights = (const float*)d_in[10];
    const float* cW1 = (const float*)d_in[11];
    const float* cb1 = (const float*)d_in[12];
    const float* cW2 = (const float*)d_in[13];
    const float* cb2 = (const float*)d_in[14];
    float* out = (float*)d_out;

    int B = in_sizes[0] / 16;  // 524288
    qnn_setup_kernel<<<1, 256>>>(qweights);
    qnn_main_kernel<<<B / NT, NT>>>(text, image, tW1, tb1, tW2, tb2,
                                    iW1, ib1, iW2, ib2,
                                    cW1, cb1, cW2, cb2, out);
}

// round 6
// speedup vs baseline: 1.4355x; 1.3555x over previous
#include <cuda_runtime.h>
#include <cuda_bf16.h>

#define NQ 4
#define NL 2
#define NT 256
#define SPB (2 * NT)   // samples per block

typedef unsigned long long ull;

__device__ float d_A[256];  // Re(U^dag Z0 U), 16x16 symmetric

__device__ __forceinline__ ull pack2(float lo, float hi) {
    ull r; asm("mov.b64 %0, {%1, %2};" : "=l"(r) : "f"(lo), "f"(hi)); return r;
}
__device__ __forceinline__ ull dup2(float x) { return pack2(x, x); }
__device__ __forceinline__ void unpack2(ull v, float& lo, float& hi) {
    asm("mov.b64 {%0, %1}, %2;" : "=f"(lo), "=f"(hi) : "l"(v));
}
__device__ __forceinline__ ull ffma2(ull a, ull b, ull c) {
    ull d; asm("fma.rn.f32x2 %0, %1, %2, %3;" : "=l"(d) : "l"(a), "l"(b), "l"(c)); return d;
}
__device__ __forceinline__ ull fmul2(ull a, ull b) {
    ull d; asm("mul.rn.f32x2 %0, %1, %2;" : "=l"(d) : "l"(a), "l"(b)); return d;
}

__device__ __forceinline__ float2 cmul(float2 a, float2 b) {
    return make_float2(a.x * b.x - a.y * b.y, a.x * b.y + a.y * b.x);
}
__device__ __forceinline__ float2 cadd(float2 a, float2 b) {
    return make_float2(a.x + b.x, a.y + b.y);
}

// Build fixed 16x16 circuit unitary from qweights, then A = Re(U^dag Z0 U).
__global__ void qnn_setup_kernel(const float* __restrict__ qw) {
    __shared__ float2 U[16][16];
    int t = threadIdx.x;  // 256 threads
    {
        int r = t >> 4, c = t & 15;
        U[r][c] = make_float2(r == c ? 1.f : 0.f, 0.f);
    }
    __syncthreads();

    for (int l = 0; l < NL; l++) {
        for (int i = 0; i < NQ; i++) {
            float phi = qw[(l * NQ + i) * 3 + 0];
            float th  = qw[(l * NQ + i) * 3 + 1];
            float om  = qw[(l * NQ + i) * 3 + 2];
            float ct = cosf(0.5f * th), st = sinf(0.5f * th);
            float ap = 0.5f * (phi + om), am = 0.5f * (phi - om);
            float cap = cosf(ap), sap = sinf(ap);
            float cam = cosf(am), sam = sinf(am);
            float2 g00 = make_float2( cap * ct, -sap * ct);
            float2 g01 = make_float2(-cam * st, -sam * st);
            float2 g10 = make_float2( cam * st, -sam * st);
            float2 g11 = make_float2( cap * ct,  sap * ct);
            int bit = 3 - i;
            if (t < 128) {
                int pair = t >> 4;
                int c = t & 15;
                int low = pair & ((1 << bit) - 1);
                int hi  = pair >> bit;
                int r0  = (hi << (bit + 1)) | low;
                int r1  = r0 | (1 << bit);
                float2 u0 = U[r0][c], u1 = U[r1][c];
                U[r0][c] = cadd(cmul(g00, u0), cmul(g01, u1));
                U[r1][c] = cadd(cmul(g10, u0), cmul(g11, u1));
            }
            __syncthreads();
        }
        {
            int r = t >> 4, c = t & 15;
            float sign = 1.f;
            if (((r >> 3) & 1) && ((r >> 2) & 1)) sign = -sign;
            if (((r >> 2) & 1) && ((r >> 1) & 1)) sign = -sign;
            if (((r >> 1) & 1) && (r & 1))        sign = -sign;
            U[r][c].x *= sign;
            U[r][c].y *= sign;
        }
        __syncthreads();
    }

    int j = t >> 4, k = t & 15;
    float acc = 0.f;
    #pragma unroll
    for (int r = 0; r < 16; r++) {
        float z = (r & 8) ? -1.f : 1.f;
        acc += z * (U[r][j].x * U[r][k].x + U[r][j].y * U[r][k].y);
    }
    d_A[j * 16 + k] = acc;
}

__global__ __launch_bounds__(NT, 2) void qnn_main_kernel(
    const float* __restrict__ text, const float* __restrict__ image,
    const float* __restrict__ tW1, const float* __restrict__ tb1,
    const float* __restrict__ tW2, const float* __restrict__ tb2,
    const float* __restrict__ iW1, const float* __restrict__ ib1,
    const float* __restrict__ iW2, const float* __restrict__ ib2,
    const float* __restrict__ cW1, const float* __restrict__ cb1,
    const float* __restrict__ cW2, const float* __restrict__ cb2,
    float* __restrict__ out)
{
    __shared__ __align__(16) float s_tW1[16 * 32];
    __shared__ __align__(16) float s_tb1[32];
    __shared__ __align__(16) float s_tW2[32 * 4];
    __shared__ __align__(16) float s_iW1[48 * 64];
    __shared__ __align__(16) float s_ib1[64];
    __shared__ __align__(16) float s_iW2[64 * 4];
    __shared__ __align__(16) float s_A[256];
    __shared__ float s_tb2[4], s_ib2[4];
    __shared__ float s_cW1[16], s_cb1[16], s_cW2[32], s_cb2[2];

    int tid = threadIdx.x;
    for (int i = tid; i < 512; i += NT) s_tW1[i] = tW1[i];
    for (int i = tid; i < 3072; i += NT) s_iW1[i] = iW1[i];
    for (int i = tid; i < 256; i += NT) { s_iW2[i] = iW2[i]; s_A[i] = d_A[i]; }
    for (int i = tid; i < 128; i += NT) s_tW2[i] = tW2[i];
    if (tid < 64) s_ib1[tid] = ib1[tid];
    if (tid < 32) { s_tb1[tid] = tb1[tid]; s_cW2[tid] = cW2[tid]; }
    if (tid < 16) { s_cW1[tid] = cW1[tid]; s_cb1[tid] = cb1[tid]; }
    if (tid < 4) { s_tb2[tid] = tb2[tid]; s_ib2[tid] = ib2[tid]; }
    if (tid < 2) s_cb2[tid] = cb2[tid];
    __syncthreads();

    int b0 = blockIdx.x * SPB + tid;       // sample 0
    int b1 = b0 + NT;                      // sample 1

    float fb0 = s_tb2[0] + s_ib2[0];
    float fb1 = s_tb2[1] + s_ib2[1];
    float fb2 = s_tb2[2] + s_ib2[2];
    float fb3 = s_tb2[3] + s_ib2[3];
    float a00 = fb0, a01 = fb1, a02 = fb2, a03 = fb3;   // feats sample 0
    float a10 = fb0, a11 = fb1, a12 = fb2, a13 = fb3;   // feats sample 1

    // ---- text MLP: 16 -> 32 (relu) -> 4; 2 samples, 2 j-passes of 16 ----
    {
        float tx0[16], tx1[16];
        {
            const float4* p0 = (const float4*)(text + (size_t)b0 * 16);
            const float4* p1 = (const float4*)(text + (size_t)b1 * 16);
            #pragma unroll
            for (int k4 = 0; k4 < 4; k4++) {
                float4 v0 = p0[k4], v1 = p1[k4];
                tx0[4*k4+0] = v0.x; tx0[4*k4+1] = v0.y; tx0[4*k4+2] = v0.z; tx0[4*k4+3] = v0.w;
                tx1[4*k4+0] = v1.x; tx1[4*k4+1] = v1.y; tx1[4*k4+2] = v1.z; tx1[4*k4+3] = v1.w;
            }
        }
        #pragma unroll
        for (int jt = 0; jt < 2; jt++) {
            ull h0[8], h1[8];   // 16 hidden each
            {
                const ulonglong2* bb = (const ulonglong2*)&s_tb1[jt * 16];
                #pragma unroll
                for (int p = 0; p < 4; p++) {
                    ulonglong2 v = bb[p];
                    h0[2*p] = v.x; h0[2*p+1] = v.y;
                    h1[2*p] = v.x; h1[2*p+1] = v.y;
                }
            }
            #pragma unroll
            for (int k = 0; k < 16; k++) {
                ull xd0 = dup2(tx0[k]);
                ull xd1 = dup2(tx1[k]);
                const ulonglong2* wrow = (const ulonglong2*)&s_tW1[k * 32 + jt * 16];
                #pragma unroll
                for (int p = 0; p < 4; p++) {
                    ulonglong2 w = wrow[p];
                    h0[2*p]   = ffma2(xd0, w.x, h0[2*p]);
                    h0[2*p+1] = ffma2(xd0, w.y, h0[2*p+1]);
                    h1[2*p]   = ffma2(xd1, w.x, h1[2*p]);
                    h1[2*p+1] = ffma2(xd1, w.y, h1[2*p+1]);
                }
            }
            // second layer rows [jt*16, jt*16+16)
            #pragma unroll
            for (int m = 0; m < 8; m++) {
                int r = jt * 16 + 2 * m;
                float4 w0 = *(const float4*)&s_tW2[r * 4];
                float4 w1 = *(const float4*)&s_tW2[(r + 1) * 4];
                float ha0, hb0, ha1, hb1;
                unpack2(h0[m], ha0, hb0); unpack2(h1[m], ha1, hb1);
                ha0 = fmaxf(ha0, 0.f); hb0 = fmaxf(hb0, 0.f);
                ha1 = fmaxf(ha1, 0.f); hb1 = fmaxf(hb1, 0.f);
                a00 = fmaf(ha0, w0.x, a00); a01 = fmaf(ha0, w0.y, a01);
                a02 = fmaf(ha0, w0.z, a02); a03 = fmaf(ha0, w0.w, a03);
                a00 = fmaf(hb0, w1.x, a00); a01 = fmaf(hb0, w1.y, a01);
                a02 = fmaf(hb0, w1.z, a02); a03 = fmaf(hb0, w1.w, a03);
                a10 = fmaf(ha1, w0.x, a10); a11 = fmaf(ha1, w0.y, a11);
                a12 = fmaf(ha1, w0.z, a12); a13 = fmaf(ha1, w0.w, a13);
                a10 = fmaf(hb1, w1.x, a10); a11 = fmaf(hb1, w1.y, a11);
                a12 = fmaf(hb1, w1.z, a12); a13 = fmaf(hb1, w1.w, a13);
            }
        }
    }

    // ---- image MLP: 48 -> 64 (relu) -> 4; 2 samples, 2 j-passes of 32 ----
    {
        const float4* p0 = (const float4*)(image + (size_t)b0 * 48);
        const float4* p1 = (const float4*)(image + (size_t)b1 * 48);
        #pragma unroll
        for (int jt = 0; jt < 2; jt++) {
            ull h0[16], h1[16];   // 32 hidden each
            {
                const ulonglong2* bb = (const ulonglong2*)&s_ib1[jt * 32];
                #pragma unroll
                for (int p = 0; p < 8; p++) {
                    ulonglong2 v = bb[p];
                    h0[2*p] = v.x; h0[2*p+1] = v.y;
                    h1[2*p] = v.x; h1[2*p+1] = v.y;
                }
            }
            #pragma unroll 4
            for (int kb = 0; kb < 12; kb++) {
                float4 v0 = p0[kb];   // gmem (L1/L2 hit on 2nd pass)
                float4 v1 = p1[kb];
                float xs0[4] = {v0.x, v0.y, v0.z, v0.w};
                float xs1[4] = {v1.x, v1.y, v1.z, v1.w};
                #pragma unroll
                for (int kk = 0; kk < 4; kk++) {
                    int k = 4 * kb + kk;
                    ull xd0 = dup2(xs0[kk]);
                    ull xd1 = dup2(xs1[kk]);
                    const ulonglong2* wrow = (const ulonglong2*)&s_iW1[k * 64 + jt * 32];
                    #pragma unroll
                    for (int p = 0; p < 8; p++) {
                        ulonglong2 w = wrow[p];
                        h0[2*p]   = ffma2(xd0, w.x, h0[2*p]);
                        h0[2*p+1] = ffma2(xd0, w.y, h0[2*p+1]);
                        h1[2*p]   = ffma2(xd1, w.x, h1[2*p]);
                        h1[2*p+1] = ffma2(xd1, w.y, h1[2*p+1]);
                    }
                }
            }
            // second layer rows [jt*32, jt*32+32)
            #pragma unroll
            for (int m = 0; m < 16; m++) {
                int r = jt * 32 + 2 * m;
                float4 w0 = *(const float4*)&s_iW2[r * 4];
                float4 w1 = *(const float4*)&s_iW2[(r + 1) * 4];
                float ha0, hb0, ha1, hb1;
                unpack2(h0[m], ha0, hb0); unpack2(h1[m], ha1, hb1);
                ha0 = fmaxf(ha0, 0.f); hb0 = fmaxf(hb0, 0.f);
                ha1 = fmaxf(ha1, 0.f); hb1 = fmaxf(hb1, 0.f);
                a00 = fmaf(ha0, w0.x, a00); a01 = fmaf(ha0, w0.y, a01);
                a02 = fmaf(ha0, w0.z, a02); a03 = fmaf(ha0, w0.w, a03);
                a00 = fmaf(hb0, w1.x, a00); a01 = fmaf(hb0, w1.y, a01);
                a02 = fmaf(hb0, w1.z, a02); a03 = fmaf(hb0, w1.w, a03);
                a10 = fmaf(ha1, w0.x, a10); a11 = fmaf(ha1, w0.y, a11);
                a12 = fmaf(ha1, w0.z, a12); a13 = fmaf(ha1, w0.w, a13);
                a10 = fmaf(hb1, w1.x, a10); a11 = fmaf(hb1, w1.y, a11);
                a12 = fmaf(hb1, w1.z, a12); a13 = fmaf(hb1, w1.w, a13);
            }
        }
    }

    // ---- quantum: half-angle = 0.25*acc; psi = outer product of cos/sin ----
    ull psi2a[8], psi2b[8];   // 16 amplitudes per sample, packed
    {
        float cc[4], ss[4];
        float a0[4] = {0.25f * a00, 0.25f * a01, 0.25f * a02, 0.25f * a03};
        #pragma unroll
        for (int i = 0; i < 4; i++) __sincosf(a0[i], &ss[i], &cc[i]);
        float e01[4] = {cc[0]*cc[1], cc[0]*ss[1], ss[0]*cc[1], ss[0]*ss[1]};
        ull e23a = pack2(cc[2]*cc[3], cc[2]*ss[3]);
        ull e23b = pack2(ss[2]*cc[3], ss[2]*ss[3]);
        #pragma unroll
        for (int j = 0; j < 4; j++) {
            ull ed = dup2(e01[j]);
            psi2a[2*j]   = fmul2(ed, e23a);
            psi2a[2*j+1] = fmul2(ed, e23b);
        }
        float a1[4] = {0.25f * a10, 0.25f * a11, 0.25f * a12, 0.25f * a13};
        #pragma unroll
        for (int i = 0; i < 4; i++) __sincosf(a1[i], &ss[i], &cc[i]);
        float f01[4] = {cc[0]*cc[1], cc[0]*ss[1], ss[0]*cc[1], ss[0]*ss[1]};
        ull f23a = pack2(cc[2]*cc[3], cc[2]*ss[3]);
        ull f23b = pack2(ss[2]*cc[3], ss[2]*ss[3]);
        #pragma unroll
        for (int j = 0; j < 4; j++) {
            ull ed = dup2(f01[j]);
            psi2b[2*j]   = fmul2(ed, f23a);
            psi2b[2*j+1] = fmul2(ed, f23b);
        }
    }

    float q0 = 0.f, q1 = 0.f;
    #pragma unroll
    for (int j = 0; j < 16; j++) {
        const ulonglong2* arow = (const ulonglong2*)&s_A[j * 16];
        ull t0 = 0ULL, t1 = 0ULL;
        #pragma unroll
        for (int p = 0; p < 4; p++) {
            ulonglong2 a2 = arow[p];     // shared load for both samples
            t0 = ffma2(psi2a[2*p],   a2.x, t0);
            t0 = ffma2(psi2a[2*p+1], a2.y, t0);
            t1 = ffma2(psi2b[2*p],   a2.x, t1);
            t1 = ffma2(psi2b[2*p+1], a2.y, t1);
        }
        float ta, tb, pj_lo, pj_hi;
        unpack2(t0, ta, tb);
        unpack2(psi2a[j >> 1], pj_lo, pj_hi);
        q0 = fmaf((j & 1) ? pj_hi : pj_lo, ta + tb, q0);
        unpack2(t1, ta, tb);
        unpack2(psi2b[j >> 1], pj_lo, pj_hi);
        q1 = fmaf((j & 1) ? pj_hi : pj_lo, ta + tb, q1);
    }

    // ---- classifier: q -> 16 (relu) -> 2; shared weight loads ----
    float o00 = s_cb2[0], o01 = s_cb2[1];
    float o10 = s_cb2[0], o11 = s_cb2[1];
    #pragma unroll
    for (int m = 0; m < 16; m++) {
        float w = s_cW1[m], bb = s_cb1[m];
        float w20 = s_cW2[2*m], w21 = s_cW2[2*m+1];
        float h0 = fmaxf(fmaf(q0, w, bb), 0.f);
        float h1 = fmaxf(fmaf(q1, w, bb), 0.f);
        o00 = fmaf(h0, w20, o00); o01 = fmaf(h0, w21, o01);
        o10 = fmaf(h1, w20, o10); o11 = fmaf(h1, w21, o11);
    }
    ((float2*)out)[b0] = make_float2(o00, o01);
    ((float2*)out)[b1] = make_float2(o10, o11);
}

extern "C" void kernel_launch(void* const* d_in, const int* in_sizes, int n_in,
                              void* d_out, int out_size) {
    const float* text = (const float*)d_in[0];
    const float* image = (const float*)d_in[1];
    const float* tW1 = (const float*)d_in[2];
    const float* tb1 = (const float*)d_in[3];
    const float* tW2 = (const float*)d_in[4];
    const float* tb2 = (const float*)d_in[5];
    const float* iW1 = (const float*)d_in[6];
    const float* ib1 = (const float*)d_in[7];
    const float* iW2 = (const float*)d_in[8];
    const float* ib2 = (const float*)d_in[9];
    const float* qweights = (const float*)d_in[10];
    const float* cW1 = (const float*)d_in[11];
    const float* cb1 = (const float*)d_in[12];
    const float* cW2 = (const float*)d_in[13];
    const float* cb2 = (const float*)d_in[14];
    float* out = (float*)d_out;

    int B = in_sizes[0] / 16;  // 524288
    qnn_setup_kernel<<<1, 256>>>(qweights);
    qnn_main_kernel<<<B / SPB, NT>>>(text, image, tW1, tb1, tW2, tb2,
                                     iW1, ib1, iW2, ib2,
                                     cW1, cb1, cW2, cb2, out);
}